// round 5
// baseline (speedup 1.0000x reference)
#include <cuda_runtime.h>

// Pair_83811991814342
// in:  (1, 1024, 260) fp32; only first 512 rows used
// out: (1, 512*512, 522) fp32 : [x[i](260) | x[j](260) | r1 | r2]

#define NROWS 512
#define DIM   260
#define HD    130            // float2 per input row
#define HC    261            // float2 per output row (522/2)
#define TI    8
#define TJ    8
#define NT    288

__global__ __launch_bounds__(NT)
void pair_kernel(const float* __restrict__ in, float* __restrict__ out) {
    __shared__ float2 s_r[TI * TJ];     // (r1, r2) per pair in the tile

    const int bi = blockIdx.y * TI;
    const int bj = blockIdx.x * TJ;
    const int c  = threadIdx.x;         // float2 column in output row

    // ---- Threads 0..63 compute (r1, r2) into smem ----
    if (c < TI * TJ) {
        int il = c >> 3, jl = c & 7;
        const float4 bi4 = __ldg(reinterpret_cast<const float4*>(
            in + (bi + il) * DIM + (DIM - 4)));
        const float4 bj4 = __ldg(reinterpret_cast<const float4*>(
            in + (bj + jl) * DIM + (DIM - 4)));
        float w = fmaxf(0.0f, fminf(bi4.z, bj4.z) - fmaxf(bi4.x, bj4.x));
        float h = fmaxf(0.0f, fminf(bi4.w, bj4.w) - fmaxf(bi4.y, bj4.y));
        float inter = w * h;
        float ai = (bi4.z - bi4.x) * (bi4.w - bi4.y);
        float aj = (bj4.z - bj4.x) * (bj4.w - bj4.y);
        s_r[c] = make_float2(inter / ai, inter / aj);
    }
    __syncthreads();

    float2* ob = reinterpret_cast<float2*>(out)
               + (size_t)(bi * NROWS + bj) * HC + c;

    if (c < 2 * HD) {
        // ---- Data columns: preload 8 values, then pure SEL + STG.64 loop ----
        const bool lo = (c < HD);
        const float2* src = reinterpret_cast<const float2*>(in)
                          + (lo ? (bi * HD + c) : (bj * HD + (c - HD)));
        float2 v[8];
        #pragma unroll
        for (int r = 0; r < 8; r++) v[r] = __ldg(&src[r * HD]);

        #pragma unroll
        for (int il = 0; il < TI; il++) {
            #pragma unroll
            for (int jl = 0; jl < TJ; jl++) {
                __stcs(&ob[(size_t)(il * NROWS + jl) * HC], lo ? v[il] : v[jl]);
            }
        }
    } else if (c == 2 * HD) {
        // ---- r1r2 column: read precomputed pairs from smem ----
        #pragma unroll
        for (int il = 0; il < TI; il++) {
            #pragma unroll
            for (int jl = 0; jl < TJ; jl++) {
                __stcs(&ob[(size_t)(il * NROWS + jl) * HC], s_r[(il << 3) | jl]);
            }
        }
    }
}

extern "C" void kernel_launch(void* const* d_in, const int* in_sizes, int n_in,
                              void* d_out, int out_size) {
    const float* in = (const float*)d_in[0];
    float* out = (float*)d_out;
    dim3 grid(NROWS / TJ, NROWS / TI);  // 64 x 64 blocks
    pair_kernel<<<grid, NT>>>(in, out);
}

// round 6
// speedup vs baseline: 1.1781x; 1.1781x over previous
#include <cuda_runtime.h>

// Pair_83811991814342
// in:  (1, 1024, 260) fp32; only first 512 rows used
// out: (1, 512*512, 522) fp32 : [x[i](260) | x[j](260) | r1 | r2]

#define NROWS 512
#define DIM   260
#define HD    130            // float2 per input row
#define HC    261            // float2 per output row (522/2)
#define TI    8
#define TJ    8
#define NT    288

__global__ __launch_bounds__(NT)
void pair_kernel(const float* __restrict__ in, float* __restrict__ out) {
    __shared__ float2 s_r[TI * TJ];     // (r1, r2) per pair in the tile

    const int bi = blockIdx.y * TI;
    const int bj = blockIdx.x * TJ;
    const int c  = threadIdx.x;         // float2 column in output row

    // ---- Threads 0..63 compute (r1, r2) into smem ----
    if (c < TI * TJ) {
        int il = c >> 3, jl = c & 7;
        const float4 bi4 = __ldg(reinterpret_cast<const float4*>(
            in + (bi + il) * DIM + (DIM - 4)));
        const float4 bj4 = __ldg(reinterpret_cast<const float4*>(
            in + (bj + jl) * DIM + (DIM - 4)));
        float w = fmaxf(0.0f, fminf(bi4.z, bj4.z) - fmaxf(bi4.x, bj4.x));
        float h = fmaxf(0.0f, fminf(bi4.w, bj4.w) - fmaxf(bi4.y, bj4.y));
        float inter = w * h;
        float ai = (bi4.z - bi4.x) * (bi4.w - bi4.y);
        float aj = (bj4.z - bj4.x) * (bj4.w - bj4.y);
        s_r[c] = make_float2(inter / ai, inter / aj);
    }
    __syncthreads();

    float2* ob = reinterpret_cast<float2*>(out)
               + (size_t)(bi * NROWS + bj) * HC + c;

    if (c < 2 * HD) {
        // ---- Data columns: preload 8 values, then pure SEL + STG.64 loop ----
        const bool lo = (c < HD);
        const float2* src = reinterpret_cast<const float2*>(in)
                          + (lo ? (bi * HD + c) : (bj * HD + (c - HD)));
        float2 v[8];
        #pragma unroll
        for (int r = 0; r < 8; r++) v[r] = __ldg(&src[r * HD]);

        #pragma unroll
        for (int il = 0; il < TI; il++) {
            #pragma unroll
            for (int jl = 0; jl < TJ; jl++) {
                ob[(size_t)(il * NROWS + jl) * HC] = lo ? v[il] : v[jl];
            }
        }
    } else if (c == 2 * HD) {
        // ---- r1r2 column: store precomputed pairs from smem ----
        #pragma unroll
        for (int il = 0; il < TI; il++) {
            #pragma unroll
            for (int jl = 0; jl < TJ; jl++) {
                ob[(size_t)(il * NROWS + jl) * HC] = s_r[(il << 3) | jl];
            }
        }
    }
}

extern "C" void kernel_launch(void* const* d_in, const int* in_sizes, int n_in,
                              void* d_out, int out_size) {
    const float* in = (const float*)d_in[0];
    float* out = (float*)d_out;
    dim3 grid(NROWS / TJ, NROWS / TI);  // 64 x 64 blocks
    pair_kernel<<<grid, NT>>>(in, out);
}

// round 8
// speedup vs baseline: 1.3113x; 1.1131x over previous
#include <cuda_runtime.h>

// Pair_83811991814342
// in:  (1, 1024, 260) fp32; only first 512 rows used
// out: (1, 512*512, 522) fp32 : [x[i](260) | x[j](260) | r1 | r2]
// Output row = 2088 B (== 8 mod 16): even global rows are 16B-aligned,
// odd rows are 8-shifted. All stores are STG.128 (plus one float2 per row).

#define NROWS 512
#define DIM   260
#define TI    8
#define TJ    8
#define NT    160            // 131 active column threads
#define RSTR  264            // smem row stride in floats (1056 B, 16B-mult)

__global__ __launch_bounds__(NT)
void pair_kernel(const float* __restrict__ in, float* __restrict__ out) {
    __shared__ float  s_rows[16][RSTR];   // rows 0-7: i-rows, 8-15: j-rows
    __shared__ float2 s_r[TI * TJ];       // (r1, r2) per (il, jl)

    const int bi = blockIdx.y * TI;
    const int bj = blockIdx.x * TJ;
    const int c  = threadIdx.x;

    // ---- Stage the 16 source rows into smem (float4 vectorized) ----
    for (int t = c; t < 16 * 65; t += NT) {
        int r = t / 65;
        int q = t - r * 65;
        int g = (r < 8) ? (bi + r) : (bj + (r - 8));
        *reinterpret_cast<float4*>(&s_rows[r][4 * q]) =
            __ldg(reinterpret_cast<const float4*>(in + g * DIM) + q);
    }

    // ---- Threads 0..63: (r1, r2) table ----
    if (c < TI * TJ) {
        int il = c >> 3, jl = c & 7;
        const float4 a = __ldg(reinterpret_cast<const float4*>(
            in + (bi + il) * DIM + (DIM - 4)));
        const float4 b = __ldg(reinterpret_cast<const float4*>(
            in + (bj + jl) * DIM + (DIM - 4)));
        float w = fmaxf(0.0f, fminf(a.z, b.z) - fmaxf(a.x, b.x));
        float h = fmaxf(0.0f, fminf(a.w, b.w) - fmaxf(a.y, b.y));
        float inter = w * h;
        s_r[c] = make_float2(inter / ((a.z - a.x) * (a.w - a.y)),
                             inter / ((b.z - b.x) * (b.w - b.y)));
    }
    __syncthreads();

    // Output base for this tile (byte arithmetic)
    char* const obBase = reinterpret_cast<char*>(out)
                       + (size_t)(bi * NROWS + bj) * (2 * DIM + 2) * 4;
    const char* const srow = reinterpret_cast<const char*>(&s_rows[0][0]);
    const char* const sjrow = srow + 8 * (RSTR * 4);
    const char* const srr  = reinterpret_cast<const char*>(&s_r[0]);

    if (c < 130) {
        // ---- Per-thread generic (base, il-step, jl-step) source descriptors ----
        // EVEN rows: quad c = floats [4c, 4c+4)
        const char* sE; int stEi, stEj;
        if (c < 65) { sE = srow  + 16 * c;        stEi = RSTR * 4; stEj = 0; }
        else        { sE = sjrow + 16 * (c - 65); stEi = 0;        stEj = RSTR * 4; }
        // ODD rows: quad c = floats [4c+2, 4c+6); lo2 = [4c+2,4c+4), hi2 = [4c+4,4c+6)
        const char* sL; int stLi, stLj;
        if (c < 65) { sL = srow  + 16 * c + 8;        stLi = RSTR * 4; stLj = 0; }
        else        { sL = sjrow + 16 * (c - 65) + 8; stLi = 0;        stLj = RSTR * 4; }
        const char* sH; int stHi, stHj;
        if (c < 64)       { sH = srow  + 16 * c + 16;        stHi = RSTR * 4; stHj = 0; }
        else if (c == 64) { sH = sjrow;                      stHi = 0;        stHj = RSTR * 4; }
        else if (c < 129) { sH = sjrow + 16 * (c - 65) + 16; stHi = 0;        stHj = RSTR * 4; }
        else              { sH = srr;                        stHi = 64;       stHj = 8; } // (r1,r2)

        char* const obE = obBase + 16 * c;       // even rows: 16B-aligned
        char* const obO = obBase + 16 * c + 8;   // odd rows: base+8 -> 16B-aligned

        #pragma unroll
        for (int il = 0; il < TI; il++) {
            #pragma unroll
            for (int jl = 0; jl < TJ; jl++) {
                const size_t off = (size_t)(il * NROWS + jl) * ((2 * DIM + 2) * 4);
                if ((jl & 1) == 0) {
                    float4 q = *reinterpret_cast<const float4*>(sE + il * stEi + jl * stEj);
                    *reinterpret_cast<float4*>(obE + off) = q;
                } else {
                    float2 lo = *reinterpret_cast<const float2*>(sL + il * stLi + jl * stLj);
                    float2 hi = *reinterpret_cast<const float2*>(sH + il * stHi + jl * stHj);
                    *reinterpret_cast<float4*>(obO + off) =
                        make_float4(lo.x, lo.y, hi.x, hi.y);
                }
            }
        }
    } else if (c == 130) {
        // Even rows: tail (r1,r2) at byte 2080. Odd rows: head x[i][0:2] at byte 0.
        #pragma unroll
        for (int il = 0; il < TI; il++) {
            #pragma unroll
            for (int jl = 0; jl < TJ; jl++) {
                const size_t off = (size_t)(il * NROWS + jl) * ((2 * DIM + 2) * 4);
                if ((jl & 1) == 0) {
                    *reinterpret_cast<float2*>(obBase + off + 2080) = s_r[(il << 3) | jl];
                } else {
                    *reinterpret_cast<float2*>(obBase + off) =
                        *reinterpret_cast<const float2*>(srow + il * (RSTR * 4));
                }
            }
        }
    }
}

extern "C" void kernel_launch(void* const* d_in, const int* in_sizes, int n_in,
                              void* d_out, int out_size) {
    const float* in = (const float*)d_in[0];
    float* out = (float*)d_out;
    dim3 grid(NROWS / TJ, NROWS / TI);  // 64 x 64 blocks
    pair_kernel<<<grid, NT>>>(in, out);
}

// round 9
// speedup vs baseline: 1.4041x; 1.0708x over previous
#include <cuda_runtime.h>

// Pair_83811991814342
// in:  (1, 1024, 260) fp32; only first 512 rows used
// out: (1, 512*512, 522) fp32 : [x[i](260) | x[j](260) | r1 | r2]
// Output row = 2088 B (== 8 mod 16): even rows 16B-aligned, odd rows 8-shifted.
// STG.128 everywhere; (column, il-half) thread split for occupancy.

#define NROWS 512
#define DIM   260
#define TI    8
#define TJ    8
#define NT    288
#define RSTR  264            // smem row stride in floats (1056 B)
#define ROWB  ((2 * DIM + 2) * 4)   // 2088 output bytes per row

__global__ __launch_bounds__(NT)
void pair_kernel(const float* __restrict__ in, float* __restrict__ out) {
    __shared__ float  s_rows[16][RSTR];   // rows 0-7: i-rows, 8-15: j-rows
    __shared__ float2 s_r[TI * TJ];       // (r1, r2) per (il, jl)

    const int bi = blockIdx.y * TI;
    const int bj = blockIdx.x * TJ;
    const int t  = threadIdx.x;

    // ---- Stage the 16 source rows into smem (float4 vectorized) ----
    for (int u = t; u < 16 * 65; u += NT) {
        int r = u / 65;
        int q = u - r * 65;
        int g = (r < 8) ? (bi + r) : (bj + (r - 8));
        *reinterpret_cast<float4*>(&s_rows[r][4 * q]) =
            __ldg(reinterpret_cast<const float4*>(in + g * DIM) + q);
    }

    // ---- Threads 0..63: (r1, r2) table ----
    if (t < TI * TJ) {
        int il = t >> 3, jl = t & 7;
        const float4 a = __ldg(reinterpret_cast<const float4*>(
            in + (bi + il) * DIM + (DIM - 4)));
        const float4 b = __ldg(reinterpret_cast<const float4*>(
            in + (bj + jl) * DIM + (DIM - 4)));
        float w = fmaxf(0.0f, fminf(a.z, b.z) - fmaxf(a.x, b.x));
        float h = fmaxf(0.0f, fminf(a.w, b.w) - fmaxf(a.y, b.y));
        float inter = w * h;
        s_r[t] = make_float2(inter / ((a.z - a.x) * (a.w - a.y)),
                             inter / ((b.z - b.x) * (b.w - b.y)));
    }
    __syncthreads();

    if (t >= 262) return;
    const int  c    = (t < 131) ? t : t - 131;   // quad column [0,131)
    const int  il0  = (t < 131) ? 0 : 4;         // il half

    char* const obBase = reinterpret_cast<char*>(out)
                       + (size_t)(bi * NROWS + bj) * ROWB;
    const char* const srow  = reinterpret_cast<const char*>(&s_rows[0][0]);
    const char* const sjrow = srow + 8 * (RSTR * 4);
    const char* const srr   = reinterpret_cast<const char*>(&s_r[0]);

    if (c < 130) {
        // EVEN rows: quad c = output floats [4c, 4c+4)
        const char* sE; int stEi, stEj;
        if (c < 65) { sE = srow  + 16 * c;        stEi = RSTR * 4; stEj = 0; }
        else        { sE = sjrow + 16 * (c - 65); stEi = 0;        stEj = RSTR * 4; }
        // ODD rows: quad c = floats [4c+2, 4c+6) = lo2 + hi2
        const char* sL; int stLi, stLj;
        if (c < 65) { sL = srow  + 16 * c + 8;        stLi = RSTR * 4; stLj = 0; }
        else        { sL = sjrow + 16 * (c - 65) + 8; stLi = 0;        stLj = RSTR * 4; }
        const char* sH; int stHi, stHj;
        if (c < 64)       { sH = srow  + 16 * c + 16;        stHi = RSTR * 4; stHj = 0; }
        else if (c == 64) { sH = sjrow;                      stHi = 0;        stHj = RSTR * 4; }
        else if (c < 129) { sH = sjrow + 16 * (c - 65) + 16; stHi = 0;        stHj = RSTR * 4; }
        else              { sH = srr;                        stHi = 64;       stHj = 8; } // (r1,r2)

        char* const obE = obBase + 16 * c;       // even rows: 16B-aligned
        char* const obO = obBase + 16 * c + 8;   // odd rows: +8 -> 16B-aligned

        #pragma unroll
        for (int k = 0; k < 4; k++) {
            const int il = il0 + k;
            #pragma unroll
            for (int jl = 0; jl < TJ; jl++) {
                const size_t off = (size_t)(il * NROWS + jl) * ROWB;
                if ((jl & 1) == 0) {
                    *reinterpret_cast<float4*>(obE + off) =
                        *reinterpret_cast<const float4*>(sE + il * stEi + jl * stEj);
                } else {
                    float2 lo = *reinterpret_cast<const float2*>(sL + il * stLi + jl * stLj);
                    float2 hi = *reinterpret_cast<const float2*>(sH + il * stHi + jl * stHj);
                    *reinterpret_cast<float4*>(obO + off) =
                        make_float4(lo.x, lo.y, hi.x, hi.y);
                }
            }
        }
    } else {
        // c == 130: even rows -> tail (r1,r2) at byte 2080; odd rows -> head x[i][0:2]
        #pragma unroll
        for (int k = 0; k < 4; k++) {
            const int il = il0 + k;
            #pragma unroll
            for (int jl = 0; jl < TJ; jl++) {
                const size_t off = (size_t)(il * NROWS + jl) * ROWB;
                if ((jl & 1) == 0) {
                    *reinterpret_cast<float2*>(obBase + off + 2080) = s_r[(il << 3) | jl];
                } else {
                    *reinterpret_cast<float2*>(obBase + off) =
                        *reinterpret_cast<const float2*>(srow + il * (RSTR * 4));
                }
            }
        }
    }
}

extern "C" void kernel_launch(void* const* d_in, const int* in_sizes, int n_in,
                              void* d_out, int out_size) {
    const float* in = (const float*)d_in[0];
    float* out = (float*)d_out;
    dim3 grid(NROWS / TJ, NROWS / TI);  // 64 x 64 blocks
    pair_kernel<<<grid, NT>>>(in, out);
}